// round 15
// baseline (speedup 1.0000x reference)
#include <cuda_runtime.h>
#include <math.h>

#define TILE   32
#define HALO   34
#define HH     (HALO*HALO)
#define CHN    12
#define HIDDEN 128
#define PERC   36
#define OUTC   9
#define HW     256
#define PIX    (HW*HW)

// pass-1 smem (floats)
#define OFF_X     0                       // 12*34*34 = 13872
#define OFF_LIST  (OFF_X + CHN*HH)        // 1024 u16 = 512 floats
#define OFF_CNT   (OFF_LIST + 512)
#define OFF_GBASE (OFF_CNT + 1)
#define SMEM1_FLOATS (OFF_GBASE + 1)
#define SMEM1_BYTES  (SMEM1_FLOATS * 4)   // ~56.2 KB -> 3 blocks/SM

typedef unsigned int u32;

// ---- global scratch (static __device__ = sanctioned, sized for worst case) ----
// A-fragment-order perc: [group][jk 0..4][half 0..1][lane 0..31] uint2
__device__ uint2 g_percf[65536 * 320];    // 167.8 MB
__device__ u32   g_pid[1048576];          // 4 MB   (b*PIX + pix)
__device__ int   g_cnt;
// fragment-order weights
__device__ uint2 g_w1f[16*5*32];          // 20 KB
__device__ uint2 g_w2f[16*2*32];          //  8 KB

__device__ __forceinline__ u32 f2tf32(float f) {
    u32 r; asm("cvt.rna.tf32.f32 %0, %1;" : "=r"(r) : "f"(f)); return r;
}
__device__ __forceinline__ float fsqrt_ap(float x) {
    float r; asm("sqrt.approx.f32 %0, %1;" : "=f"(r) : "f"(x)); return r;
}
__device__ __forceinline__ void mma_tf32(float& d0, float& d1, float& d2, float& d3,
                                         u32 a0, u32 a1, u32 a2, u32 a3,
                                         u32 b0, u32 b1) {
    asm("mma.sync.aligned.m16n8k8.row.col.f32.tf32.tf32.f32 "
        "{%0,%1,%2,%3}, {%4,%5,%6,%7}, {%8,%9}, {%0,%1,%2,%3};"
        : "+f"(d0), "+f"(d1), "+f"(d2), "+f"(d3)
        : "r"(a0), "r"(a1), "r"(a2), "r"(a3), "r"(b0), "r"(b1));
}

// ---------------- repack: weights -> fragment order; zero counter ----------------
__global__ void __launch_bounds__(256)
isoca_repack_kernel(const float* __restrict__ w1w, const float* __restrict__ w2w)
{
    const int tid = blockIdx.x * blockDim.x + threadIdx.x;
    const int nth = gridDim.x * blockDim.x;
    if (tid == 0) g_cnt = 0;
    for (int i = tid; i < 16*5*32; i += nth) {
        int l = i & 31, jk = (i >> 5) % 5, tile = i / (5*32);
        int lg = l >> 2, lt = l & 3;
        int h = tile * 8 + lg, k0 = 8*jk + lt, k1 = k0 + 4;
        uint2 v;
        v.x = f2tf32(w1w[h * PERC + k0]);
        v.y = (k1 < PERC) ? f2tf32(w1w[h * PERC + k1]) : 0u;
        g_w1f[i] = v;
    }
    // w2 PERMUTED: k-slot lt -> h0+2lt, slot lt+4 -> h0+2lt+1 (layer-1 D feeds layer-2)
    for (int i = tid; i < 16*2*32; i += nth) {
        int l = i & 31, jo = (i >> 5) & 1, tile = i >> 6;
        int lg = l >> 2, lt = l & 3;
        int o = jo * 8 + lg, h0 = tile * 8;
        uint2 v = make_uint2(0u, 0u);
        if (o < OUTC) {
            v.x = f2tf32(w2w[o * HIDDEN + h0 + 2*lt    ]);
            v.y = f2tf32(w2w[o * HIDDEN + h0 + 2*lt + 1]);
        }
        g_w2f[i] = v;
    }
}

// ---------------- pass 1: stencil + mask + compact + perc->fragments ----------------
__global__ void __launch_bounds__(256, 3)
isoca_pass1_kernel(const float* __restrict__ x,
                   const float* __restrict__ rnd,
                   float* __restrict__ out)
{
    extern __shared__ float sm[];
    float* s_x = sm + OFF_X;
    unsigned short* s_list = (unsigned short*)(sm + OFF_LIST);
    int* s_cnt   = (int*)(sm + OFF_CNT);
    int* s_gbase = (int*)(sm + OFF_GBASE);

    const int b    = blockIdx.z;
    const int ty0  = blockIdx.y * TILE;
    const int tx0  = blockIdx.x * TILE;
    const int tid  = threadIdx.x;
    const int lane = tid & 31;

    if (tid == 0) *s_cnt = 0;

    // stage x tile: interior rows via LDG.128, halo columns scalar
    const float* xb = x + (size_t)b * CHN * PIX;
    for (int i = tid; i < CHN * HALO * 8; i += 256) {
        const int q = i & 7, row = i >> 3;
        const int c = row / HALO, yy = row - c * HALO;
        const int gy = (ty0 + yy - 1) & (HW - 1);
        float4 v = *(const float4*)(xb + (size_t)c * PIX + (size_t)gy * HW + tx0 + 4*q);
        float* dst = s_x + c * HH + yy * HALO + 1 + 4*q;
        dst[0] = v.x; dst[1] = v.y; dst[2] = v.z; dst[3] = v.w;
    }
    for (int i = tid; i < CHN * HALO * 2; i += 256) {
        const int side = i & 1, row = i >> 1;
        const int c = row / HALO, yy = row - c * HALO;
        const int gy = (ty0 + yy - 1) & (HW - 1);
        const int gx = side ? ((tx0 + TILE) & (HW - 1)) : ((tx0 - 1) & (HW - 1));
        s_x[c * HH + yy * HALO + (side ? HALO - 1 : 0)] =
            xb[(size_t)c * PIX + (size_t)gy * HW + gx];
    }
    __syncthreads();

    float* ob = out + (size_t)b * CHN * PIX;
    const bool interior = (blockIdx.x != 0) && (blockIdx.x != gridDim.x - 1) &&
                          (blockIdx.y != 0) && (blockIdx.y != gridDim.y - 1);

    // mask + ballot compaction: 4 consecutive-x pixels / thread, 1 atomic / warp
    {
        const int aty  = tid >> 3;
        const int atx0 = (tid & 7) << 2;
        const float4 rv4 = *(const float4*)(rnd + (size_t)b * PIX +
                                            (size_t)(ty0 + aty) * HW + tx0 + atx0);
        const float rv[4] = {rv4.x, rv4.y, rv4.z, rv4.w};
        const float* r3 = s_x + 3*HH + aty * HALO + atx0;
        float mx[4];
        if (interior) {
            float cm[6];
            #pragma unroll
            for (int j = 0; j < 6; j++)
                cm[j] = fmaxf(fmaxf(r3[j], r3[HALO + j]), r3[2*HALO + j]);
            #pragma unroll
            for (int it = 0; it < 4; it++)
                mx[it] = fmaxf(fmaxf(cm[it], cm[it+1]), cm[it+2]);
        } else {
            #pragma unroll
            for (int it = 0; it < 4; it++) {
                const int gy = ty0 + aty, gx = tx0 + atx0 + it;
                float m = -INFINITY;
                #pragma unroll
                for (int dy = -1; dy <= 1; dy++)
                    #pragma unroll
                    for (int dx = -1; dx <= 1; dx++) {
                        int Y = gy + dy, X = gx + dx;
                        if (Y >= 0 && Y < HW && X >= 0 && X < HW)
                            m = fmaxf(m, r3[(1+dy)*HALO + it + (1+dx)]);
                    }
                mx[it] = m;
            }
        }
        u32 bals[4]; int cnts[4];
        #pragma unroll
        for (int it = 0; it < 4; it++) {
            const bool active = (mx[it] > 0.1f) && ((rv[it] + 0.5f) >= 1.0f);
            bals[it] = __ballot_sync(0xffffffffu, active);
            cnts[it] = __popc(bals[it]);
        }
        const int total = cnts[0] + cnts[1] + cnts[2] + cnts[3];
        int pos = 0;
        if (lane == 0 && total) pos = atomicAdd(s_cnt, total);
        pos = __shfl_sync(0xffffffffu, pos, 0);
        const u32 ltmask = (1u << lane) - 1u;
        int off = pos;
        #pragma unroll
        for (int it = 0; it < 4; it++) {
            if (bals[it] & (1u << lane))
                s_list[off + __popc(bals[it] & ltmask)] =
                    (unsigned short)(aty * 32 + atx0 + it);
            off += cnts[it];
        }
    }

    // unconditional copy-all: out = x (pass 2 adds y to active pixels later)
    {
        const int cty = tid >> 3, ctx = (tid & 7) << 2;
        const size_t cpix = (size_t)(ty0 + cty) * HW + (tx0 + ctx);
        #pragma unroll
        for (int c = 0; c < CHN; c++) {
            float4 v = *(const float4*)(xb + (size_t)c * PIX + cpix);
            *(float4*)(ob + (size_t)c * PIX + cpix) = v;
        }
    }
    __syncthreads();

    // reserve global compacted range
    if (tid == 0) {
        const int nb = *s_cnt;
        *s_gbase = nb ? atomicAdd(&g_cnt, nb) : 0;
    }
    __syncthreads();
    const int nblk  = *s_cnt;
    const int gbase = *s_gbase;

    // active pixels: compute perc, scatter into fragment layout
    for (int i = tid; i < nblk; i += 256) {
        const int p   = s_list[i];
        const int pty = p >> 5, ptx = p & 31;
        const int idx = gbase + i;

        float perc[PERC];
        #pragma unroll
        for (int c = 0; c < CHN; c++) {
            const float* r0 = s_x + c * HH + pty * HALO + ptx;
            float n00 = r0[0],      n01 = r0[1],        n02 = r0[2];
            float n10 = r0[HALO],   n11 = r0[HALO+1],   n12 = r0[HALO+2];
            float n20 = r0[2*HALO], n21 = r0[2*HALO+1], n22 = r0[2*HALO+2];
            float lap = (n00 + n02 + n20 + n22) + 2.0f*(n01 + n10 + n12 + n21) - 12.0f*n11;
            float gxv = (n02 - n00) + 2.0f*(n12 - n10) + (n22 - n20);
            float gyv = (n20 - n00) + 2.0f*(n21 - n01) + (n22 - n02);
            perc[2*c]     = n11;
            perc[2*c + 1] = lap;
            perc[24 + c]  = fsqrt_ap(gxv*gxv + gyv*gyv + 1e-8f);
        }

        g_pid[idx] = ((u32)b << 16) | ((u32)(ty0 + pty) << 8) | (u32)(tx0 + ptx);

        const int group = idx >> 4;
        const int slot  = idx & 15;
        const int gg    = slot & 7;
        const int half  = slot >> 3;
        uint2* dst = g_percf + (size_t)group * 320 + half * 32 + 4 * gg;
        #pragma unroll
        for (int jk = 0; jk < 5; jk++) {
            u32 q0x = f2tf32(perc[8*jk + 0]);
            u32 q1x = f2tf32(perc[8*jk + 1]);
            u32 q2x = f2tf32(perc[8*jk + 2]);
            u32 q3x = f2tf32(perc[8*jk + 3]);
            u32 q0y = (8*jk + 4 < PERC) ? f2tf32(perc[8*jk + 4]) : 0u;
            u32 q1y = (8*jk + 5 < PERC) ? f2tf32(perc[8*jk + 5]) : 0u;
            u32 q2y = (8*jk + 6 < PERC) ? f2tf32(perc[8*jk + 6]) : 0u;
            u32 q3y = (8*jk + 7 < PERC) ? f2tf32(perc[8*jk + 7]) : 0u;
            uint4 v0 = make_uint4(q0x, q0y, q1x, q1y);
            uint4 v1 = make_uint4(q2x, q2y, q3x, q3y);
            *(uint4*)(dst + jk*64)     = v0;
            *(uint4*)(dst + jk*64 + 2) = v1;
        }
    }
}

// ---------------- pass 2: zero-smem GEMM over compacted pixels ----------------
__device__ __forceinline__ void load_Afrag(int group, int lane, u32 A[5][4]) {
    const uint2* base = g_percf + (size_t)group * 320 + lane;
    #pragma unroll
    for (int jk = 0; jk < 5; jk++) {
        uint2 lo = __ldg(base + jk*64);
        uint2 hi = __ldg(base + jk*64 + 32);
        A[jk][0] = lo.x;  A[jk][2] = lo.y;
        A[jk][1] = hi.x;  A[jk][3] = hi.y;
    }
}

__global__ void __launch_bounds__(256, 3)
isoca_pass2_kernel(const float* __restrict__ w1b,
                   float* __restrict__ out)
{
    const int tid  = threadIdx.x;
    const int wid  = tid >> 5;
    const int lane = tid & 31;
    const int g    = lane >> 2;
    const int t    = lane & 3;

    const int n = g_cnt;
    const int npairs = (n + 31) >> 5;

    for (int pr = blockIdx.x * 8 + wid; pr < npairs; pr += gridDim.x * 8) {
        const int base0 = pr << 5;
        const int base1 = base0 + 16;

        u32 A0[5][4], A1[5][4];
        load_Afrag(2*pr,     lane, A0);
        load_Afrag(2*pr + 1, lane, A1);   // stale if base1 >= n; rows are isolated

        float D2a[2][4] = {{0,0,0,0},{0,0,0,0}};
        float D2b[2][4] = {{0,0,0,0},{0,0,0,0}};

        #pragma unroll
        for (int tile = 0; tile < 16; tile++) {
            const float2 bb = __ldg((const float2*)(w1b + tile*8 + 2*t));
            float d0a = bb.x, d1a = bb.y, d2a = bb.x, d3a = bb.y;
            float d0b = bb.x, d1b = bb.y, d2b = bb.x, d3b = bb.y;
            const uint2* w1p = g_w1f + tile*5*32 + lane;
            #pragma unroll
            for (int jk = 0; jk < 5; jk++) {
                uint2 w = __ldg(w1p + jk*32);   // L1-resident (no smem carveout)
                mma_tf32(d0a, d1a, d2a, d3a, A0[jk][0], A0[jk][1], A0[jk][2], A0[jk][3], w.x, w.y);
                mma_tf32(d0b, d1b, d2b, d3b, A1[jk][0], A1[jk][1], A1[jk][2], A1[jk][3], w.x, w.y);
            }
            u32 a0a = f2tf32(fmaxf(d0a, 0.01f*d0a));
            u32 a2a = f2tf32(fmaxf(d1a, 0.01f*d1a));
            u32 a1a = f2tf32(fmaxf(d2a, 0.01f*d2a));
            u32 a3a = f2tf32(fmaxf(d3a, 0.01f*d3a));
            u32 a0b = f2tf32(fmaxf(d0b, 0.01f*d0b));
            u32 a2b = f2tf32(fmaxf(d1b, 0.01f*d1b));
            u32 a1b = f2tf32(fmaxf(d2b, 0.01f*d2b));
            u32 a3b = f2tf32(fmaxf(d3b, 0.01f*d3b));
            const uint2* w2p = g_w2f + tile*2*32 + lane;
            #pragma unroll
            for (int jo = 0; jo < 2; jo++) {
                uint2 w = __ldg(w2p + jo*32);
                mma_tf32(D2a[jo][0], D2a[jo][1], D2a[jo][2], D2a[jo][3],
                         a0a, a1a, a2a, a3a, w.x, w.y);
                mma_tf32(D2b[jo][0], D2b[jo][1], D2b[jo][2], D2b[jo][3],
                         a0b, a1b, a2b, a3b, w.x, w.y);
            }
        }

        #pragma unroll
        for (int grp2 = 0; grp2 < 2; grp2++) {
            const int gb = grp2 ? base1 : base0;
            float (*D2)[4] = grp2 ? D2b : D2a;
            const int i1 = gb + g;
            const int i2 = gb + g + 8;
            if (i1 < n) {
                const u32 pid = g_pid[i1];
                float* ad = out + (size_t)(pid >> 16) * CHN * PIX + (pid & 0xFFFFu);
                const int o0 = 2*t;
                ad[(size_t)o0     * PIX] += D2[0][0];
                ad[(size_t)(o0+1) * PIX] += D2[0][1];
                if (t == 0) ad[(size_t)8 * PIX] += D2[1][0];
            }
            if (i2 < n) {
                const u32 pid = g_pid[i2];
                float* ad = out + (size_t)(pid >> 16) * CHN * PIX + (pid & 0xFFFFu);
                const int o0 = 2*t;
                ad[(size_t)o0     * PIX] += D2[0][2];
                ad[(size_t)(o0+1) * PIX] += D2[0][3];
                if (t == 0) ad[(size_t)8 * PIX] += D2[1][2];
            }
        }
    }
}

extern "C" void kernel_launch(void* const* d_in, const int* in_sizes, int n_in,
                              void* d_out, int out_size) {
    const float* x   = (const float*)d_in[0];
    const float* rnd = (const float*)d_in[1];
    const float* w1w = (const float*)d_in[2];
    const float* w1b = (const float*)d_in[3];
    const float* w2w = (const float*)d_in[4];
    float* out = (float*)d_out;

    cudaFuncSetAttribute(isoca_pass1_kernel,
                         cudaFuncAttributeMaxDynamicSharedMemorySize, SMEM1_BYTES);

    isoca_repack_kernel<<<16, 256>>>(w1w, w2w);
    dim3 grid1(HW / TILE, HW / TILE, 16);
    isoca_pass1_kernel<<<grid1, 256, SMEM1_BYTES>>>(x, rnd, out);
    isoca_pass2_kernel<<<444, 256>>>(w1b, out);
}

// round 16
// speedup vs baseline: 2.0493x; 2.0493x over previous
#include <cuda_runtime.h>
#include <math.h>

#define TILE   32
#define HALO   34   // TILE + 2
#define HH     (HALO*HALO)
#define CHN    12
#define HIDDEN 128
#define PERC   36
#define OUTC   9
#define HW     256
#define PIX    (HW*HW)

#define WSTRIDE 36   // wbuf slot stride (4g+t mod 32 distinct -> conflict-free)

// dynamic smem layout (float units) — weights live in GLOBAL scratch (L2-resident)
#define OFF_X     0                          // 12*34*34 = 13872
#define OFF_B     (OFF_X + CHN*HH)           // 128 (fp32 bias)
#define OFF_LIST  (OFF_B + HIDDEN)           // 1024 u16 = 512 floats (128 per warp)
#define OFF_WBUF  (OFF_LIST + 512)           // 8 warps * 16*36 u32 = 4608
#define SMEM_FLOATS (OFF_WBUF + 8*16*WSTRIDE)
#define SMEM_BYTES  (SMEM_FLOATS * 4)        // ~74.7 KB -> 3 blocks/SM

typedef unsigned int u32;

// fragment-order weights (written once per launch by repack kernel)
__device__ uint2 g_w1f[16*5*32];   // 20 KB
__device__ uint2 g_w2f[16*2*32];   //  8 KB

__device__ __forceinline__ u32 f2tf32(float f) {
    u32 r; asm("cvt.rna.tf32.f32 %0, %1;" : "=r"(r) : "f"(f)); return r;
}
__device__ __forceinline__ float fsqrt_ap(float x) {
    float r; asm("sqrt.approx.f32 %0, %1;" : "=f"(r) : "f"(x)); return r;
}
__device__ __forceinline__ void mma_tf32(float& d0, float& d1, float& d2, float& d3,
                                         u32 a0, u32 a1, u32 a2, u32 a3,
                                         u32 b0, u32 b1) {
    asm("mma.sync.aligned.m16n8k8.row.col.f32.tf32.tf32.f32 "
        "{%0,%1,%2,%3}, {%4,%5,%6,%7}, {%8,%9}, {%0,%1,%2,%3};"
        : "+f"(d0), "+f"(d1), "+f"(d2), "+f"(d3)
        : "r"(a0), "r"(a1), "r"(a2), "r"(a3), "r"(b0), "r"(b1));
}

// ---------- repack kernel: weights -> fragment-order tf32 in global scratch ----------
__global__ void __launch_bounds__(256)
isoca_repack_kernel(const float* __restrict__ w1w, const float* __restrict__ w2w)
{
    const int tid = blockIdx.x * blockDim.x + threadIdx.x;
    const int nth = gridDim.x * blockDim.x;
    for (int i = tid; i < 16*5*32; i += nth) {
        int l = i & 31, jk = (i >> 5) % 5, tile = i / (5*32);
        int lg = l >> 2, lt = l & 3;
        int h = tile * 8 + lg, k0 = 8*jk + lt, k1 = k0 + 4;
        uint2 v;
        v.x = f2tf32(w1w[h * PERC + k0]);
        v.y = (k1 < PERC) ? f2tf32(w1w[h * PERC + k1]) : 0u;
        g_w1f[i] = v;
    }
    // w2 PERMUTED: k-slot lt -> h0+2lt, slot lt+4 -> h0+2lt+1 (layer-1 D feeds layer-2)
    for (int i = tid; i < 16*2*32; i += nth) {
        int l = i & 31, jo = (i >> 5) & 1, tile = i >> 6;
        int lg = l >> 2, lt = l & 3;
        int o = jo * 8 + lg, h0 = tile * 8;
        uint2 v = make_uint2(0u, 0u);
        if (o < OUTC) {
            v.x = f2tf32(w2w[o * HIDDEN + h0 + 2*lt    ]);
            v.y = f2tf32(w2w[o * HIDDEN + h0 + 2*lt + 1]);
        }
        g_w2f[i] = v;
    }
}

// stage perc for 16 pixel slots into wbuf (tf32 bits), lane = (slot 0..15, half 0..1)
__device__ __forceinline__ void stage_perc(u32* wbuf, const float* s_x,
                                           const unsigned short* wlist,
                                           int base, int n, int lane)
{
    const int slot = lane & 15;
    const int half = lane >> 4;
    int pi = base + slot; if (pi >= n) pi = n - 1;   // clamp (stores guarded later)
    const int pp = wlist[pi];
    const int pty = pp >> 5, ptx = pp & 31;
    #pragma unroll
    for (int j = 0; j < 6; j++) {
        const int c = half * 6 + j;
        const float* r0 = s_x + c * HH + pty * HALO + ptx;
        float n00 = r0[0],      n01 = r0[1],        n02 = r0[2];
        float n10 = r0[HALO],   n11 = r0[HALO+1],   n12 = r0[HALO+2];
        float n20 = r0[2*HALO], n21 = r0[2*HALO+1], n22 = r0[2*HALO+2];
        float lap = (n00 + n02 + n20 + n22) + 2.0f*(n01 + n10 + n12 + n21) - 12.0f*n11;
        float gxv = (n02 - n00) + 2.0f*(n12 - n10) + (n22 - n20);
        float gyv = (n20 - n00) + 2.0f*(n21 - n01) + (n22 - n02);
        float gn  = fsqrt_ap(gxv*gxv + gyv*gyv + 1e-8f);
        *(uint2*)(wbuf + slot*WSTRIDE + 2*c) = make_uint2(f2tf32(n11), f2tf32(lap));
        wbuf[slot*WSTRIDE + 24 + c] = f2tf32(gn);
    }
}

__device__ __forceinline__ void load_A(const u32* wbuf, int g, int t, u32 A[5][4]) {
    #pragma unroll
    for (int jk = 0; jk < 5; jk++) {
        A[jk][0] = wbuf[ g    *WSTRIDE + 8*jk + t    ];
        A[jk][1] = wbuf[(g+8) *WSTRIDE + 8*jk + t    ];
        A[jk][2] = (jk < 4) ? wbuf[ g    *WSTRIDE + 8*jk + t + 4] : 0u;
        A[jk][3] = (jk < 4) ? wbuf[(g+8) *WSTRIDE + 8*jk + t + 4] : 0u;
    }
}

__global__ void __launch_bounds__(256, 3)
isoca_fused_kernel(const float* __restrict__ x,
                   const float* __restrict__ rnd,
                   const float* __restrict__ w1b,
                   float* __restrict__ out)
{
    extern __shared__ float sm[];
    float* s_x = sm + OFF_X;
    float* s_b = sm + OFF_B;
    unsigned short* s_list = (unsigned short*)(sm + OFF_LIST);

    const int b    = blockIdx.z;
    const int ty0  = blockIdx.y * TILE;
    const int tx0  = blockIdx.x * TILE;
    const int tid  = threadIdx.x;
    const int wid  = tid >> 5;
    const int lane = tid & 31;
    const int g    = lane >> 2;
    const int t    = lane & 3;

    if (tid < HIDDEN) s_b[tid] = w1b[tid];

    // ---- stage x tile (+1 halo, circular wrap) ----
    const float* xb = x + (size_t)b * CHN * PIX;
    for (int i = tid; i < CHN * HH; i += 256) {
        int c  = i / HH;
        int r  = i % HH;
        int yy = r / HALO;
        int xx = r % HALO;
        int gyw = (ty0 + yy - 1) & (HW - 1);
        int gxw = (tx0 + xx - 1) & (HW - 1);
        s_x[c * HH + yy * HALO + xx] = xb[(size_t)c * PIX + gyw * HW + gxw];
    }
    __syncthreads();   // the ONLY block-wide barrier

    // ======== Phase A (warp-autonomous): warp wid owns pixel rows 4wid..4wid+3 ========
    float* ob = out + (size_t)b * CHN * PIX;
    const bool interior = (blockIdx.x != 0) && (blockIdx.x != gridDim.x - 1) &&
                          (blockIdx.y != 0) && (blockIdx.y != gridDim.y - 1);
    unsigned short* wlist = s_list + wid * 128;
    const int wrow0 = wid * 4;

    int cnt = 0;
    const u32 ltmask = (1u << lane) - 1u;
    #pragma unroll
    for (int it = 0; it < 4; it++) {
        const int row = wrow0 + it;
        const float* r3 = s_x + 3*HH + row * HALO + lane;   // stencil origin (halo coords)

        float mx;
        if (interior) {
            mx =           fmaxf(fmaxf(r3[0],      r3[1]),        r3[2]);
            mx = fmaxf(mx, fmaxf(fmaxf(r3[HALO],   r3[HALO+1]),   r3[HALO+2]));
            mx = fmaxf(mx, fmaxf(fmaxf(r3[2*HALO], r3[2*HALO+1]), r3[2*HALO+2]));
        } else {
            const int gy = ty0 + row, gx = tx0 + lane;
            mx = -INFINITY;
            #pragma unroll
            for (int dy = -1; dy <= 1; dy++)
                #pragma unroll
                for (int dx = -1; dx <= 1; dx++) {
                    int Y = gy + dy, X = gx + dx;
                    if (Y >= 0 && Y < HW && X >= 0 && X < HW)
                        mx = fmaxf(mx, r3[(1+dy)*HALO + (1+dx)]);
                }
        }
        const float rv = rnd[(size_t)b * PIX + (size_t)(ty0 + row) * HW + tx0 + lane];
        const bool active = (mx > 0.1f) && ((rv + 0.5f) >= 1.0f);   // floor(rv+.5)!=0

        const u32 bal = __ballot_sync(0xffffffffu, active);
        if (active)
            wlist[cnt + __popc(bal & ltmask)] = (unsigned short)(row * 32 + lane);
        cnt += __popc(bal);
    }

    // ---- warp-local copy-all: out = x for this warp's 128 pixels ----
    // (Phase B, run by THIS warp, overwrites its active pixels afterward — program order)
    {
        const int crow = wrow0 + (lane >> 3);
        const int cqx  = (lane & 7) << 2;
        const size_t cpix = (size_t)(ty0 + crow) * HW + (tx0 + cqx);
        #pragma unroll
        for (int c = 0; c < CHN; c++) {
            const float* src = s_x + c * HH + (crow + 1) * HALO + cqx + 1;
            float4 v = make_float4(src[0], src[1], src[2], src[3]);
            *(float4*)(ob + (size_t)c * PIX + cpix) = v;
        }
    }

    // ======== Phase B (warp-autonomous): this warp's actives, 2 groups per iter ========
    if (cnt == 0) return;
    u32* wbuf = (u32*)(sm + OFF_WBUF) + wid * (16 * WSTRIDE);

    const int ngroups = (cnt + 15) >> 4;
    const int npairs  = (ngroups + 1) >> 1;
    for (int pr = 0; pr < npairs; pr++) {
        const int base0 = pr << 5;
        const int base1 = base0 + 16;

        stage_perc(wbuf, s_x, wlist, base0, cnt, lane);
        __syncwarp();
        u32 A0[5][4]; load_A(wbuf, g, t, A0);
        __syncwarp();
        stage_perc(wbuf, s_x, wlist, base1, cnt, lane);   // clamped if base1 >= cnt
        __syncwarp();
        u32 A1[5][4]; load_A(wbuf, g, t, A1);

        float D2a[2][4] = {{0,0,0,0},{0,0,0,0}};
        float D2b[2][4] = {{0,0,0,0},{0,0,0,0}};

        #pragma unroll
        for (int tile = 0; tile < 16; tile++) {
            float2 bb = *(const float2*)(s_b + tile*8 + 2*t);
            float d0a = bb.x, d1a = bb.y, d2a = bb.x, d3a = bb.y;
            float d0b = bb.x, d1b = bb.y, d2b = bb.x, d3b = bb.y;
            const uint2* w1p = g_w1f + tile*5*32 + lane;
            #pragma unroll
            for (int jk = 0; jk < 5; jk++) {
                uint2 w = __ldg(w1p + jk*32);   // L2-resident weight fragment
                mma_tf32(d0a, d1a, d2a, d3a, A0[jk][0], A0[jk][1], A0[jk][2], A0[jk][3], w.x, w.y);
                mma_tf32(d0b, d1b, d2b, d3b, A1[jk][0], A1[jk][1], A1[jk][2], A1[jk][3], w.x, w.y);
            }
            // leaky + cvt: D fragment IS the layer-2 A fragment (k-perm baked into w2f)
            u32 a0a = f2tf32(fmaxf(d0a, 0.01f*d0a));
            u32 a2a = f2tf32(fmaxf(d1a, 0.01f*d1a));
            u32 a1a = f2tf32(fmaxf(d2a, 0.01f*d2a));
            u32 a3a = f2tf32(fmaxf(d3a, 0.01f*d3a));
            u32 a0b = f2tf32(fmaxf(d0b, 0.01f*d0b));
            u32 a2b = f2tf32(fmaxf(d1b, 0.01f*d1b));
            u32 a1b = f2tf32(fmaxf(d2b, 0.01f*d2b));
            u32 a3b = f2tf32(fmaxf(d3b, 0.01f*d3b));
            const uint2* w2p = g_w2f + tile*2*32 + lane;
            #pragma unroll
            for (int jo = 0; jo < 2; jo++) {
                uint2 w = __ldg(w2p + jo*32);
                mma_tf32(D2a[jo][0], D2a[jo][1], D2a[jo][2], D2a[jo][3],
                         a0a, a1a, a2a, a3a, w.x, w.y);
                mma_tf32(D2b[jo][0], D2b[jo][1], D2b[jo][2], D2b[jo][3],
                         a0b, a1b, a2b, a3b, w.x, w.y);
            }
        }

        #pragma unroll
        for (int grp2 = 0; grp2 < 2; grp2++) {
            const int  gb = grp2 ? base1 : base0;
            float (*D2)[4] = grp2 ? D2b : D2a;
            const int i1 = gb + g;
            const int i2 = gb + g + 8;
            if (i1 < cnt) {
                const int pp = wlist[i1];
                const int pty = pp >> 5, ptx = pp & 31;
                const size_t apix = (size_t)(ty0 + pty) * HW + (tx0 + ptx);
                const int o0 = 2*t;
                ob[(size_t)o0     * PIX + apix] = s_x[o0    *HH + (pty+1)*HALO + ptx+1] + D2[0][0];
                ob[(size_t)(o0+1) * PIX + apix] = s_x[(o0+1)*HH + (pty+1)*HALO + ptx+1] + D2[0][1];
                if (t == 0)
                    ob[(size_t)8 * PIX + apix] = s_x[8*HH + (pty+1)*HALO + ptx+1] + D2[1][0];
            }
            if (i2 < cnt) {
                const int pp = wlist[i2];
                const int pty = pp >> 5, ptx = pp & 31;
                const size_t apix = (size_t)(ty0 + pty) * HW + (tx0 + ptx);
                const int o0 = 2*t;
                ob[(size_t)o0     * PIX + apix] = s_x[o0    *HH + (pty+1)*HALO + ptx+1] + D2[0][2];
                ob[(size_t)(o0+1) * PIX + apix] = s_x[(o0+1)*HH + (pty+1)*HALO + ptx+1] + D2[0][3];
                if (t == 0)
                    ob[(size_t)8 * PIX + apix] = s_x[8*HH + (pty+1)*HALO + ptx+1] + D2[1][2];
            }
        }
    }
}

extern "C" void kernel_launch(void* const* d_in, const int* in_sizes, int n_in,
                              void* d_out, int out_size) {
    const float* x   = (const float*)d_in[0];
    const float* rnd = (const float*)d_in[1];
    const float* w1w = (const float*)d_in[2];
    const float* w1b = (const float*)d_in[3];
    const float* w2w = (const float*)d_in[4];
    float* out = (float*)d_out;

    cudaFuncSetAttribute(isoca_fused_kernel,
                         cudaFuncAttributeMaxDynamicSharedMemorySize, SMEM_BYTES);

    isoca_repack_kernel<<<16, 256>>>(w1w, w2w);

    dim3 grid(HW / TILE, HW / TILE, 16);   // (8, 8, 16) = 1024 blocks
    isoca_fused_kernel<<<grid, 256, SMEM_BYTES>>>(x, rnd, w1b, out);
}

// round 17
// speedup vs baseline: 2.2445x; 1.0952x over previous
#include <cuda_runtime.h>
#include <math.h>

#define TILE   32
#define HALO   34   // TILE + 2
#define HH     (HALO*HALO)
#define CHN    12
#define HIDDEN 128
#define PERC   36
#define OUTC   9
#define HW     256
#define PIX    (HW*HW)

#define WSTRIDE 36   // wbuf slot stride (4g+t mod 32 distinct -> conflict-free)

// dynamic smem layout (float units) — weights live in GLOBAL scratch (L2-resident)
#define OFF_X     0                          // 12*34*34 = 13872
#define OFF_B     (OFF_X + CHN*HH)           // 128 (fp32 bias)
#define OFF_LIST  (OFF_B + HIDDEN)           // 1024 u16 = 512 floats
#define OFF_CNT   (OFF_LIST + 512)           // 4 (pad)
#define OFF_WBUF  (OFF_CNT + 4)              // 8 warps * 16*36 u32 = 4608
#define SMEM_FLOATS (OFF_WBUF + 8*16*WSTRIDE)
#define SMEM_BYTES  (SMEM_FLOATS * 4)        // ~74.7 KB -> 3 blocks/SM

typedef unsigned int u32;

// fragment-order weights (written once per launch by repack kernel)
__device__ uint2 g_w1f[16*5*32];   // 20 KB
__device__ uint2 g_w2f[16*2*32];   //  8 KB

__device__ __forceinline__ u32 f2tf32(float f) {
    u32 r; asm("cvt.rna.tf32.f32 %0, %1;" : "=r"(r) : "f"(f)); return r;
}
__device__ __forceinline__ float fsqrt_ap(float x) {
    float r; asm("sqrt.approx.f32 %0, %1;" : "=f"(r) : "f"(x)); return r;
}

__device__ __forceinline__ void mma_tf32(float& d0, float& d1, float& d2, float& d3,
                                         u32 a0, u32 a1, u32 a2, u32 a3,
                                         u32 b0, u32 b1) {
    asm("mma.sync.aligned.m16n8k8.row.col.f32.tf32.tf32.f32 "
        "{%0,%1,%2,%3}, {%4,%5,%6,%7}, {%8,%9}, {%0,%1,%2,%3};"
        : "+f"(d0), "+f"(d1), "+f"(d2), "+f"(d3)
        : "r"(a0), "r"(a1), "r"(a2), "r"(a3), "r"(b0), "r"(b1));
}

// ---------- repack kernel: weights -> fragment-order tf32 in global scratch ----------
__global__ void __launch_bounds__(256)
isoca_repack_kernel(const float* __restrict__ w1w, const float* __restrict__ w2w)
{
    const int tid = blockIdx.x * blockDim.x + threadIdx.x;
    const int nth = gridDim.x * blockDim.x;
    for (int i = tid; i < 16*5*32; i += nth) {
        int l    = i & 31;
        int jk   = (i >> 5) % 5;
        int tile = i / (5*32);
        int lg = l >> 2, lt = l & 3;
        int h  = tile * 8 + lg;
        int k0 = 8*jk + lt;
        int k1 = k0 + 4;
        uint2 v;
        v.x = f2tf32(w1w[h * PERC + k0]);
        v.y = (k1 < PERC) ? f2tf32(w1w[h * PERC + k1]) : 0u;
        g_w1f[i] = v;
    }
    // w2 PERMUTED: k-slot lt -> h0+2lt, slot lt+4 -> h0+2lt+1, so layer-1 D regs
    // feed layer-2 directly as A fragments.
    for (int i = tid; i < 16*2*32; i += nth) {
        int l    = i & 31;
        int jo   = (i >> 5) & 1;
        int tile = i >> 6;
        int lg = l >> 2, lt = l & 3;
        int o  = jo * 8 + lg;
        int h0 = tile * 8;
        uint2 v = make_uint2(0u, 0u);
        if (o < OUTC) {
            v.x = f2tf32(w2w[o * HIDDEN + h0 + 2*lt    ]);
            v.y = f2tf32(w2w[o * HIDDEN + h0 + 2*lt + 1]);
        }
        g_w2f[i] = v;
    }
}

// stage perc for 16 pixel slots into wbuf (tf32 bits), lane = (slot 0..15, half 0..1)
__device__ __forceinline__ void stage_perc(u32* wbuf, const float* s_x,
                                           const unsigned short* s_list,
                                           int base, int n, int lane)
{
    const int slot = lane & 15;
    const int half = lane >> 4;
    int pi = base + slot; if (pi >= n) pi = n - 1;   // clamp (stores guarded later)
    const int pp = s_list[pi];
    const int pty = pp >> 5, ptx = pp & 31;
    #pragma unroll
    for (int j = 0; j < 6; j++) {
        const int c = half * 6 + j;
        const float* r0 = s_x + c * HH + pty * HALO + ptx;
        float n00 = r0[0],      n01 = r0[1],        n02 = r0[2];
        float n10 = r0[HALO],   n11 = r0[HALO+1],   n12 = r0[HALO+2];
        float n20 = r0[2*HALO], n21 = r0[2*HALO+1], n22 = r0[2*HALO+2];
        float lap = (n00 + n02 + n20 + n22) + 2.0f*(n01 + n10 + n12 + n21) - 12.0f*n11;
        float gxv = (n02 - n00) + 2.0f*(n12 - n10) + (n22 - n20);
        float gyv = (n20 - n00) + 2.0f*(n21 - n01) + (n22 - n02);
        float gn  = fsqrt_ap(gxv*gxv + gyv*gyv + 1e-8f);
        *(uint2*)(wbuf + slot*WSTRIDE + 2*c) = make_uint2(f2tf32(n11), f2tf32(lap));
        wbuf[slot*WSTRIDE + 24 + c] = f2tf32(gn);
    }
}

__device__ __forceinline__ void load_A(const u32* wbuf, int g, int t, u32 A[5][4]) {
    #pragma unroll
    for (int jk = 0; jk < 5; jk++) {
        A[jk][0] = wbuf[ g    *WSTRIDE + 8*jk + t    ];
        A[jk][1] = wbuf[(g+8) *WSTRIDE + 8*jk + t    ];
        A[jk][2] = (jk < 4) ? wbuf[ g    *WSTRIDE + 8*jk + t + 4] : 0u;
        A[jk][3] = (jk < 4) ? wbuf[(g+8) *WSTRIDE + 8*jk + t + 4] : 0u;
    }
}

__global__ void __launch_bounds__(256, 3)
isoca_fused_kernel(const float* __restrict__ x,
                   const float* __restrict__ rnd,
                   const float* __restrict__ w1b,
                   float* __restrict__ out)
{
    extern __shared__ float sm[];
    float* s_x   = sm + OFF_X;
    float* s_b   = sm + OFF_B;
    unsigned short* s_list = (unsigned short*)(sm + OFF_LIST);
    int*   s_cnt = (int*)(sm + OFF_CNT);

    const int b    = blockIdx.z;
    const int ty0  = blockIdx.y * TILE;
    const int tx0  = blockIdx.x * TILE;
    const int tid  = threadIdx.x;
    const int wid  = tid >> 5;
    const int lane = tid & 31;
    const int g    = lane >> 2;
    const int t    = lane & 3;

    if (tid == 0) *s_cnt = 0;
    if (tid < HIDDEN) s_b[tid] = w1b[tid];

    // ---- stage x tile (+1 halo, circular wrap) ----
    const float* xb = x + (size_t)b * CHN * PIX;
    for (int i = tid; i < CHN * HH; i += 256) {
        int c  = i / HH;
        int r  = i % HH;
        int yy = r / HALO;
        int xx = r % HALO;
        int gyw = (ty0 + yy - 1) & (HW - 1);
        int gxw = (tx0 + xx - 1) & (HW - 1);
        s_x[c * HH + yy * HALO + xx] = xb[(size_t)c * PIX + gyw * HW + gxw];
    }
    __syncthreads();

    // =========================== Phase A ===========================
    float* ob = out + (size_t)b * CHN * PIX;
    const bool interior = (blockIdx.x != 0) && (blockIdx.x != gridDim.x - 1) &&
                          (blockIdx.y != 0) && (blockIdx.y != gridDim.y - 1);

    // -- mask + warp-ballot compaction (4 pixels / thread) --
    #pragma unroll
    for (int it = 0; it < 4; it++) {
        const int p  = tid + it * 256;
        const int ty = p >> 5;
        const int tx = p & 31;
        const float* r3 = s_x + 3*HH + ty * HALO + tx;

        float mx;
        if (interior) {
            mx =            fmaxf(fmaxf(r3[0],      r3[1]),      r3[2]);
            mx = fmaxf(mx,  fmaxf(fmaxf(r3[HALO],   r3[HALO+1]), r3[HALO+2]));
            mx = fmaxf(mx,  fmaxf(fmaxf(r3[2*HALO], r3[2*HALO+1]), r3[2*HALO+2]));
        } else {
            const int gy = ty0 + ty, gx = tx0 + tx;
            mx = -INFINITY;
            #pragma unroll
            for (int dy = -1; dy <= 1; dy++)
                #pragma unroll
                for (int dx = -1; dx <= 1; dx++) {
                    int Y = gy + dy, X = gx + dx;
                    if (Y >= 0 && Y < HW && X >= 0 && X < HW)
                        mx = fmaxf(mx, r3[(1+dy)*HALO + (1+dx)]);
                }
        }
        const float rv = rnd[(size_t)b * PIX + (size_t)(ty0 + ty) * HW + (tx0 + tx)];
        const bool active = (mx > 0.1f) && ((rv + 0.5f) >= 1.0f);   // floor(rv+.5)!=0

        const u32 bal = __ballot_sync(0xffffffffu, active);
        const int cnt = __popc(bal);
        int pos = 0;
        if (cnt) {
            if (lane == 0) pos = atomicAdd(s_cnt, cnt);
            pos = __shfl_sync(0xffffffffu, pos, 0);
            if (active)
                s_list[pos + __popc(bal & ((1u << lane) - 1u))] = (unsigned short)p;
        }
    }

    // -- unconditional copy-all (float4); Phase B overwrites active pixels after barrier --
    for (int i = tid; i < CHN * 256; i += 256) {
        const int c  = i >> 8;
        const int r  = i & 255;
        const int ty = r >> 3;
        const int tx = (r & 7) << 2;
        const float* src = s_x + c * HH + (ty + 1) * HALO + tx + 1;
        float4 v = make_float4(src[0], src[1], src[2], src[3]);
        *(float4*)(ob + (size_t)c * PIX + (size_t)(ty0 + ty) * HW + tx0 + tx) = v;
    }
    __syncthreads();

    // ====== Phase B: 32 pixels (2 mma groups) per warp iteration, tf32 mma ======
    const int n = *s_cnt;
    u32* wbuf = (u32*)(sm + OFF_WBUF) + wid * (16 * WSTRIDE);

    const int ngroups = (n + 15) >> 4;
    const int npairs  = (ngroups + 1) >> 1;
    for (int pr = wid; pr < npairs; pr += 8) {
        const int base0 = pr << 5;
        const int base1 = base0 + 16;

        stage_perc(wbuf, s_x, s_list, base0, n, lane);
        __syncwarp();
        u32 A0[5][4]; load_A(wbuf, g, t, A0);
        __syncwarp();
        stage_perc(wbuf, s_x, s_list, base1, n, lane);   // clamped if base1 >= n
        __syncwarp();
        u32 A1[5][4]; load_A(wbuf, g, t, A1);

        float D2a[2][4] = {{0,0,0,0},{0,0,0,0}};
        float D2b[2][4] = {{0,0,0,0},{0,0,0,0}};

        #pragma unroll
        for (int tile = 0; tile < 16; tile++) {
            float2 bb = *(const float2*)(s_b + tile*8 + 2*t);
            float d0a = bb.x, d1a = bb.y, d2a = bb.x, d3a = bb.y;
            float d0b = bb.x, d1b = bb.y, d2b = bb.x, d3b = bb.y;
            const uint2* w1p = g_w1f + tile*5*32 + lane;
            #pragma unroll
            for (int jk = 0; jk < 5; jk++) {
                uint2 w = __ldg(w1p + jk*32);   // L2-resident weight fragment
                mma_tf32(d0a, d1a, d2a, d3a, A0[jk][0], A0[jk][1], A0[jk][2], A0[jk][3], w.x, w.y);
                mma_tf32(d0b, d1b, d2b, d3b, A1[jk][0], A1[jk][1], A1[jk][2], A1[jk][3], w.x, w.y);
            }
            // leaky + cvt: D fragment IS the layer-2 A fragment (k-perm baked into w2f)
            u32 a0a = f2tf32(fmaxf(d0a, 0.01f*d0a));
            u32 a2a = f2tf32(fmaxf(d1a, 0.01f*d1a));
            u32 a1a = f2tf32(fmaxf(d2a, 0.01f*d2a));
            u32 a3a = f2tf32(fmaxf(d3a, 0.01f*d3a));
            u32 a0b = f2tf32(fmaxf(d0b, 0.01f*d0b));
            u32 a2b = f2tf32(fmaxf(d1b, 0.01f*d1b));
            u32 a1b = f2tf32(fmaxf(d2b, 0.01f*d2b));
            u32 a3b = f2tf32(fmaxf(d3b, 0.01f*d3b));
            const uint2* w2p = g_w2f + tile*2*32 + lane;
            #pragma unroll
            for (int jo = 0; jo < 2; jo++) {
                uint2 w = __ldg(w2p + jo*32);
                mma_tf32(D2a[jo][0], D2a[jo][1], D2a[jo][2], D2a[jo][3],
                         a0a, a1a, a2a, a3a, w.x, w.y);
                mma_tf32(D2b[jo][0], D2b[jo][1], D2b[jo][2], D2b[jo][3],
                         a0b, a1b, a2b, a3b, w.x, w.y);
            }
        }

        #pragma unroll
        for (int grp2 = 0; grp2 < 2; grp2++) {
            const int  gb = grp2 ? base1 : base0;
            float (*D2)[4] = grp2 ? D2b : D2a;
            const int i1 = gb + g;
            const int i2 = gb + g + 8;
            if (i1 < n) {
                const int pp = s_list[i1];
                const int pty = pp >> 5, ptx = pp & 31;
                const size_t apix = (size_t)(ty0 + pty) * HW + (tx0 + ptx);
                const int o0 = 2*t;
                ob[(size_t)o0     * PIX + apix] = s_x[o0    *HH + (pty+1)*HALO + ptx+1] + D2[0][0];
                ob[(size_t)(o0+1) * PIX + apix] = s_x[(o0+1)*HH + (pty+1)*HALO + ptx+1] + D2[0][1];
                if (t == 0)
                    ob[(size_t)8 * PIX + apix] = s_x[8*HH + (pty+1)*HALO + ptx+1] + D2[1][0];
            }
            if (i2 < n) {
                const int pp = s_list[i2];
                const int pty = pp >> 5, ptx = pp & 31;
                const size_t apix = (size_t)(ty0 + pty) * HW + (tx0 + ptx);
                const int o0 = 2*t;
                ob[(size_t)o0     * PIX + apix] = s_x[o0    *HH + (pty+1)*HALO + ptx+1] + D2[0][2];
                ob[(size_t)(o0+1) * PIX + apix] = s_x[(o0+1)*HH + (pty+1)*HALO + ptx+1] + D2[0][3];
                if (t == 0)
                    ob[(size_t)8 * PIX + apix] = s_x[8*HH + (pty+1)*HALO + ptx+1] + D2[1][2];
            }
        }
    }
}

extern "C" void kernel_launch(void* const* d_in, const int* in_sizes, int n_in,
                              void* d_out, int out_size) {
    const float* x   = (const float*)d_in[0];
    const float* rnd = (const float*)d_in[1];
    const float* w1w = (const float*)d_in[2];
    const float* w1b = (const float*)d_in[3];
    const float* w2w = (const float*)d_in[4];
    float* out = (float*)d_out;

    cudaFuncSetAttribute(isoca_fused_kernel,
                         cudaFuncAttributeMaxDynamicSharedMemorySize, SMEM_BYTES);

    isoca_repack_kernel<<<16, 256>>>(w1w, w2w);

    dim3 grid(HW / TILE, HW / TILE, 16);   // (8, 8, 16) = 1024 blocks
    isoca_fused_kernel<<<grid, 256, SMEM_BYTES>>>(x, rnd, w1b, out);
}